// round 8
// baseline (speedup 1.0000x reference)
#include <cuda_runtime.h>
#include <cuda_bf16.h>
#include <cstdint>

// Problem constants
#define BB 4
#define SS 2048
#define DD 1024
#define HH 16
#define DHD 64
#define MROWS (BB*SS)          // 8192

// -------- scratch (alloc-free rule: __device__ globals) --------
__device__ __align__(128) uint32_t g_xc[(size_t)MROWS * DD];        // x as tf32
__device__ __align__(128) uint32_t g_wqkv[(size_t)DD * 3 * DD];     // [k][3N] tf32
__device__ __align__(128) uint32_t g_wo[(size_t)DD * DD];           // [k][n] tf32
__device__ __align__(128) uint32_t g_QKV[(size_t)MROWS * 3 * DD];   // [m][3072] tf32
__device__ __align__(128) uint32_t g_ctx[(size_t)MROWS * DD];       // tf32

// ============================================================================
// helpers
// ============================================================================
__device__ __forceinline__ uint32_t f2tf32(float f) {
    uint32_t u;
    asm("cvt.rna.tf32.f32 %0, %1;" : "=r"(u) : "r"(__float_as_uint(f)));
    return u;
}

__device__ __forceinline__ void mma_tf32(float* c, const uint32_t* a, const uint32_t* b) {
    asm volatile(
        "mma.sync.aligned.m16n8k8.row.col.f32.tf32.tf32.f32 "
        "{%0,%1,%2,%3}, {%4,%5,%6,%7}, {%8,%9}, {%0,%1,%2,%3};"
        : "+f"(c[0]), "+f"(c[1]), "+f"(c[2]), "+f"(c[3])
        : "r"(a[0]), "r"(a[1]), "r"(a[2]), "r"(a[3]), "r"(b[0]), "r"(b[1]));
}

__device__ __forceinline__ void cp16(uint32_t dst, const void* src) {
    asm volatile("cp.async.cg.shared.global [%0], [%1], 16;" :: "r"(dst), "l"(src));
}

__device__ __forceinline__ uint32_t smem_u32(const void* p) {
    return (uint32_t)__cvta_generic_to_shared(p);
}

// ============================================================================
// prep: fp32 -> tf32(rna) conversions
// ============================================================================
__global__ void __launch_bounds__(256) conv_flat_kernel(
    const float* __restrict__ src, uint32_t* __restrict__ dst, int n4)
{
    int i = blockIdx.x * 256 + threadIdx.x;
    if (i >= n4) return;
    float4 v = reinterpret_cast<const float4*>(src)[i];
    uint4 o;
    o.x = f2tf32(v.x); o.y = f2tf32(v.y); o.z = f2tf32(v.z); o.w = f2tf32(v.w);
    reinterpret_cast<uint4*>(dst)[i] = o;
}

// W [1024][1024] -> dst rows stride ldo at column offset coff (tf32)
__global__ void __launch_bounds__(256) conv_w_kernel(
    const float* __restrict__ W, uint32_t* __restrict__ dst, int ldo, int coff)
{
    int i = blockIdx.x * 256 + threadIdx.x;   // 1024*256 float4s
    int k = i >> 8, n4 = (i & 255) * 4;
    float4 v = *reinterpret_cast<const float4*>(W + (size_t)k * DD + n4);
    uint4 o;
    o.x = f2tf32(v.x); o.y = f2tf32(v.y); o.z = f2tf32(v.z); o.w = f2tf32(v.w);
    *reinterpret_cast<uint4*>(dst + (size_t)k * ldo + coff + n4) = o;
}

// ============================================================================
// tf32 mma.sync GEMM, pre-converted operands.
// C[m,n] = sum_k A[m,k]*B[k,n] + bias[n]; A: Mx1024 tf32, B: 1024xN tf32.
// 128x128 CTA tile, 4 warps of 64x64 (MT=4, NT=8): 32 LDS per 32 mma per kk
// (ratio 1.0 vs 1.5 before -> smem-BW relief). 3-stage cp.async pipeline.
// OUT_TF32: store tf32 bit patterns (for downstream mma operands).
// ============================================================================
#define GBM 128
#define GBN 128
#define GBK 32
#define SA 36
#define SB 136
#define ASZ (GBM*SA)           // 4608 words
#define BSZ (GBK*SB)           // 4352 words
#define STW (ASZ+BSZ)          // words per stage = 8960
#define NST 3
#define GEMM_SMEM_BYTES (NST*STW*4)   // 107520

template<int OUT_TF32>
__global__ void __launch_bounds__(128, 2) gemm_tf32_kernel(
    const uint32_t* __restrict__ A, const uint32_t* __restrict__ B,
    const float* __restrict__ b0, const float* __restrict__ b1,
    const float* __restrict__ b2, void* __restrict__ Cv, int N)
{
    extern __shared__ uint32_t smem[];
    const uint32_t smem_u = smem_u32(smem);

    const int K = DD;
    const int tid  = threadIdx.x;
    const int wid  = tid >> 5;
    const int lane = tid & 31;
    const int g    = lane >> 2;
    const int t    = lane & 3;
    const int wm   = (wid >> 1) * 64;
    const int wn   = (wid & 1) * 64;

    const int brow = blockIdx.y * GBM;
    const int bcol = blockIdx.x * GBN;

    const uint32_t* Ag = A + (size_t)brow * K;
    const uint32_t* Bg = B + bcol;

    // gmem->smem: A 128x32 words = 1024 granules(16B); 128 thr x 8
    const int a_r0 = tid >> 3;            // +16/iter
    const int a_c  = (tid & 7) * 4;
    // B 32x128 words = 1024 granules; 128 thr x 8
    const int b_r0 = tid >> 5;            // +4/iter
    const int b_c  = (tid & 31) * 4;

    float acc[4][8][4];
    #pragma unroll
    for (int i = 0; i < 4; i++)
        #pragma unroll
        for (int j = 0; j < 8; j++)
            #pragma unroll
            for (int r = 0; r < 4; r++) acc[i][j][r] = 0.f;

    const int NIT = K / GBK;              // 32

    auto load_stage = [&](int it) {
        const int k0 = it * GBK;
        const int s = it % NST;
        const uint32_t as = smem_u + (uint32_t)(s * STW) * 4;
        const uint32_t bs = as + (uint32_t)ASZ * 4;
        #pragma unroll
        for (int i = 0; i < 8; i++) {
            const int r = a_r0 + i * 16;
            cp16(as + (uint32_t)((r * SA + a_c) * 4), Ag + (size_t)r * K + k0 + a_c);
        }
        #pragma unroll
        for (int i = 0; i < 8; i++) {
            const int r = b_r0 + i * 4;
            cp16(bs + (uint32_t)((r * SB + b_c) * 4), Bg + (size_t)(k0 + r) * N + b_c);
        }
        asm volatile("cp.async.commit_group;");
    };

    load_stage(0);
    load_stage(1);

    for (int it = 0; it < NIT; ++it) {
        if (it + 2 < NIT) {
            load_stage(it + 2);
            asm volatile("cp.async.wait_group 2;");
        } else if (it + 1 < NIT) {
            asm volatile("cp.async.wait_group 1;");
        } else {
            asm volatile("cp.async.wait_group 0;");
        }
        __syncthreads();

        const uint32_t* As_ = smem + (it % NST) * STW;
        const uint32_t* Bs_ = As_ + ASZ;

        #pragma unroll
        for (int kk = 0; kk < 4; ++kk) {
            uint32_t af[4][4], bf[8][2];
            #pragma unroll
            for (int mt = 0; mt < 4; ++mt) {
                const uint32_t* p = As_ + (size_t)(wm + mt * 16 + g) * SA + kk * 8 + t;
                af[mt][0] = p[0];
                af[mt][1] = p[8 * SA];
                af[mt][2] = p[4];
                af[mt][3] = p[8 * SA + 4];
            }
            #pragma unroll
            for (int nt = 0; nt < 8; ++nt) {
                const uint32_t* p = Bs_ + (size_t)(kk * 8 + t) * SB + wn + nt * 8 + g;
                bf[nt][0] = p[0];
                bf[nt][1] = p[4 * SB];
            }
            #pragma unroll
            for (int mt = 0; mt < 4; ++mt)
                #pragma unroll
                for (int nt = 0; nt < 8; ++nt)
                    mma_tf32(acc[mt][nt], af[mt], bf[nt]);
        }
        __syncthreads();
    }

    // epilogue: bias select (tiles never straddle 1024-col boundaries)
    const int bsel = bcol >> 10;
    const float* bias = (bsel == 0) ? b0 : (bsel == 1 ? b1 : b2);
    const int bloc = bcol & 1023;

    #pragma unroll
    for (int nt = 0; nt < 8; ++nt) {
        const int col = wn + nt * 8 + 2 * t;
        const float2 bb = *reinterpret_cast<const float2*>(&bias[bloc + col]);
        #pragma unroll
        for (int mt = 0; mt < 4; ++mt) {
            const int r0 = brow + wm + mt * 16 + g;
            float v00 = acc[mt][nt][0] + bb.x;
            float v01 = acc[mt][nt][1] + bb.y;
            float v10 = acc[mt][nt][2] + bb.x;
            float v11 = acc[mt][nt][3] + bb.y;
            if (OUT_TF32) {
                uint32_t* C = (uint32_t*)Cv;
                uint2 o0, o1;
                o0.x = f2tf32(v00); o0.y = f2tf32(v01);
                o1.x = f2tf32(v10); o1.y = f2tf32(v11);
                *reinterpret_cast<uint2*>(&C[(size_t)r0 * N + bcol + col]) = o0;
                *reinterpret_cast<uint2*>(&C[(size_t)(r0 + 8) * N + bcol + col]) = o1;
            } else {
                float* C = (float*)Cv;
                float2 o0, o1;
                o0.x = v00; o0.y = v01;
                o1.x = v10; o1.y = v11;
                *reinterpret_cast<float2*>(&C[(size_t)r0 * N + bcol + col]) = o0;
                *reinterpret_cast<float2*>(&C[(size_t)(r0 + 8) * N + bcol + col]) = o1;
            }
        }
    }
}

// ============================================================================
// Causal flash attention, tf32 mma.sync (unchanged from R5/R6).
// ============================================================================
#define SKS 68
#define SVS 72
#define SQS 136
#define O_KS 0
#define O_VS (64*SKS)
#define O_QT (O_VS + 64*SVS)
#define O_PT (O_QT + 64*SQS)
#define O_CR (O_PT + 64*SQS)
#define O_LS (O_CR + 128)
#define ATTN_SMEM_BYTES ((O_LS + 128) * 4)    // 106496

__global__ void __launch_bounds__(256, 2) attn_mma_kernel(
    const uint32_t* __restrict__ QKV, uint32_t* __restrict__ Ctx)
{
    extern __shared__ uint32_t sm[];
    uint32_t* Ks = sm + O_KS;
    uint32_t* Vs = sm + O_VS;
    uint32_t* Qt = sm + O_QT;
    uint32_t* Pts = sm + O_PT;
    float* corr_s = (float*)(sm + O_CR);
    float* l_s    = (float*)(sm + O_LS);
    const uint32_t smb = smem_u32(sm);

    const int qblk = gridDim.x - 1 - blockIdx.x;
    const int h    = blockIdx.y;
    const int b    = blockIdx.z;
    const int tid  = threadIdx.x;
    const int w    = tid >> 5;
    const int lane = tid & 31;
    const int g    = lane >> 2;
    const int t    = lane & 3;
    const int q0   = qblk * 128;

    const uint32_t* Qg = QKV + ((size_t)(b * SS + q0)) * 3072 + h * DHD;
    const uint32_t* Kg = QKV + ((size_t)(b * SS)) * 3072 + 1024 + h * DHD;
    const uint32_t* Vg = Kg + 1024;

    #pragma unroll
    for (int i = 0; i < 8; i++) {
        int idx = tid + i * 256;
        int qr = idx & 127, c4 = (idx >> 7) * 4;
        uint4 v = *reinterpret_cast<const uint4*>(Qg + (size_t)qr * 3072 + c4);
        Qt[(c4 + 0) * SQS + qr] = __float_as_uint(__uint_as_float(v.x) * 0.125f);
        Qt[(c4 + 1) * SQS + qr] = __float_as_uint(__uint_as_float(v.y) * 0.125f);
        Qt[(c4 + 2) * SQS + qr] = __float_as_uint(__uint_as_float(v.z) * 0.125f);
        Qt[(c4 + 3) * SQS + qr] = __float_as_uint(__uint_as_float(v.w) * 0.125f);
    }

    float m[4], l[4];
    #pragma unroll
    for (int j = 0; j < 4; j++) { m[j] = -1e30f; l[j] = 0.f; }
    float oc[8][4];
    #pragma unroll
    for (int nt = 0; nt < 8; nt++)
        #pragma unroll
        for (int r = 0; r < 4; r++) oc[nt][r] = 0.f;

    const int kv_r = tid >> 4;
    const int kv_c = (tid & 15) * 4;

    const int ntiles = 2 * qblk + 2;
    for (int tt = 0; tt < ntiles; tt++) {
        __syncthreads();
        {
            const uint32_t* Ktg = Kg + (size_t)(tt * 64) * 3072;
            const uint32_t* Vtg = Vg + (size_t)(tt * 64) * 3072;
            #pragma unroll
            for (int i = 0; i < 4; i++) {
                const int r = kv_r + i * 16;
                cp16(smb + (uint32_t)((O_KS + r * SKS + kv_c) * 4), Ktg + (size_t)r * 3072 + kv_c);
                cp16(smb + (uint32_t)((O_VS + r * SVS + kv_c) * 4), Vtg + (size_t)r * 3072 + kv_c);
            }
            asm volatile("cp.async.commit_group;");
            asm volatile("cp.async.wait_group 0;");
        }
        __syncthreads();

        float sc[4][2][4];
        #pragma unroll
        for (int mt = 0; mt < 4; mt++)
            #pragma unroll
            for (int nt = 0; nt < 2; nt++)
                #pragma unroll
                for (int r = 0; r < 4; r++) sc[mt][nt][r] = 0.f;

        #pragma unroll
        for (int kk = 0; kk < 8; kk++) {
            uint32_t bfq[2][2];
            #pragma unroll
            for (int nt = 0; nt < 2; nt++) {
                const int base = (kk * 8 + t) * SQS + w * 16 + nt * 8 + g;
                bfq[nt][0] = Qt[base];
                bfq[nt][1] = Qt[base + 4 * SQS];
            }
            #pragma unroll
            for (int mt = 0; mt < 4; mt++) {
                uint32_t af[4];
                const int base = (mt * 16 + g) * SKS + kk * 8 + t;
                af[0] = Ks[base];
                af[1] = Ks[base + 8 * SKS];
                af[2] = Ks[base + 4];
                af[3] = Ks[base + 8 * SKS + 4];
                mma_tf32(sc[mt][0], af, bfq[0]);
                mma_tf32(sc[mt][1], af, bfq[1]);
            }
        }

        if (tt >= 2 * qblk) {
            const int kvb = tt * 64;
            #pragma unroll
            for (int mt = 0; mt < 4; mt++)
                #pragma unroll
                for (int nt = 0; nt < 2; nt++)
                    #pragma unroll
                    for (int rh = 0; rh < 2; rh++)
                        #pragma unroll
                        for (int c = 0; c < 2; c++) {
                            int kv = kvb + mt * 16 + g + rh * 8;
                            int qq = q0 + w * 16 + nt * 8 + 2 * t + c;
                            if (kv > qq) sc[mt][nt][rh * 2 + c] = -1e30f;
                        }
        }

        float corr_loc[4];
        #pragma unroll
        for (int nt = 0; nt < 2; nt++)
            #pragma unroll
            for (int c = 0; c < 2; c++) {
                const int j = nt * 2 + c;
                float tmax = -1e30f;
                #pragma unroll
                for (int mt = 0; mt < 4; mt++) {
                    tmax = fmaxf(tmax, sc[mt][nt][c]);
                    tmax = fmaxf(tmax, sc[mt][nt][2 + c]);
                }
                tmax = fmaxf(tmax, __shfl_xor_sync(0xffffffffu, tmax, 4));
                tmax = fmaxf(tmax, __shfl_xor_sync(0xffffffffu, tmax, 8));
                tmax = fmaxf(tmax, __shfl_xor_sync(0xffffffffu, tmax, 16));
                const float mnew = fmaxf(m[j], tmax);
                corr_loc[j] = __expf(m[j] - mnew);
                m[j] = mnew;
                float ts = 0.f;
                #pragma unroll
                for (int mt = 0; mt < 4; mt++) {
                    float e0 = __expf(sc[mt][nt][c] - mnew);
                    float e1 = __expf(sc[mt][nt][2 + c] - mnew);
                    sc[mt][nt][c] = e0;
                    sc[mt][nt][2 + c] = e1;
                    ts += e0 + e1;
                }
                ts += __shfl_xor_sync(0xffffffffu, ts, 4);
                ts += __shfl_xor_sync(0xffffffffu, ts, 8);
                ts += __shfl_xor_sync(0xffffffffu, ts, 16);
                l[j] = l[j] * corr_loc[j] + ts;
            }

        if (g == 0) {
            #pragma unroll
            for (int nt = 0; nt < 2; nt++)
                #pragma unroll
                for (int c = 0; c < 2; c++)
                    corr_s[w * 16 + nt * 8 + 2 * t + c] = corr_loc[nt * 2 + c];
        }
        #pragma unroll
        for (int mt = 0; mt < 4; mt++)
            #pragma unroll
            for (int nt = 0; nt < 2; nt++)
                #pragma unroll
                for (int rh = 0; rh < 2; rh++) {
                    int row = mt * 16 + g + rh * 8;
                    int col = w * 16 + nt * 8 + 2 * t;
                    Pts[row * SQS + col]     = f2tf32(sc[mt][nt][rh * 2 + 0]);
                    Pts[row * SQS + col + 1] = f2tf32(sc[mt][nt][rh * 2 + 1]);
                }
        __syncwarp();

        const float cr0 = corr_s[w * 16 + g];
        const float cr1 = corr_s[w * 16 + g + 8];
        #pragma unroll
        for (int nt = 0; nt < 8; nt++) {
            oc[nt][0] *= cr0; oc[nt][1] *= cr0;
            oc[nt][2] *= cr1; oc[nt][3] *= cr1;
        }

        #pragma unroll
        for (int kk = 0; kk < 8; kk++) {
            uint32_t af[4];
            const int base = (kk * 8 + t) * SQS + w * 16 + g;
            af[0] = Pts[base];
            af[1] = Pts[base + 8];
            af[2] = Pts[base + 4 * SQS];
            af[3] = Pts[base + 4 * SQS + 8];
            #pragma unroll
            for (int nt = 0; nt < 8; nt++) {
                uint32_t bf[2];
                const int vb = (kk * 8 + t) * SVS + nt * 8 + g;
                bf[0] = Vs[vb];
                bf[1] = Vs[vb + 4 * SVS];
                mma_tf32(oc[nt], af, bf);
            }
        }
    }

    if (g == 0) {
        #pragma unroll
        for (int nt = 0; nt < 2; nt++)
            #pragma unroll
            for (int c = 0; c < 2; c++)
                l_s[w * 16 + nt * 8 + 2 * t + c] = l[nt * 2 + c];
    }
    __syncwarp();
    const float li0 = 1.f / l_s[w * 16 + g];
    const float li1 = 1.f / l_s[w * 16 + g + 8];

    uint32_t* Og = Ctx + ((size_t)(b * SS + q0 + w * 16)) * DD + h * DHD;
    #pragma unroll
    for (int nt = 0; nt < 8; nt++) {
        const int col = nt * 8 + 2 * t;
        uint2 v0, v1;
        v0.x = f2tf32(oc[nt][0] * li0); v0.y = f2tf32(oc[nt][1] * li0);
        v1.x = f2tf32(oc[nt][2] * li1); v1.y = f2tf32(oc[nt][3] * li1);
        *reinterpret_cast<uint2*>(Og + (size_t)g * DD + col) = v0;
        *reinterpret_cast<uint2*>(Og + (size_t)(g + 8) * DD + col) = v1;
    }
}

// ============================================================================
// launch
// ============================================================================
extern "C" void kernel_launch(void* const* d_in, const int* in_sizes, int n_in,
                              void* d_out, int out_size)
{
    const float* x  = (const float*)d_in[0];
    const float* Wq = (const float*)d_in[1];
    const float* bq = (const float*)d_in[2];
    const float* Wk = (const float*)d_in[3];
    const float* bk = (const float*)d_in[4];
    const float* Wv = (const float*)d_in[5];
    const float* bv = (const float*)d_in[6];
    const float* Wo = (const float*)d_in[7];
    const float* bo = (const float*)d_in[8];
    float* out = (float*)d_out;

    uint32_t *pxc, *pwqkv, *pwo, *pQKV, *pctx;
    cudaGetSymbolAddress((void**)&pxc, g_xc);
    cudaGetSymbolAddress((void**)&pwqkv, g_wqkv);
    cudaGetSymbolAddress((void**)&pwo, g_wo);
    cudaGetSymbolAddress((void**)&pQKV, g_QKV);
    cudaGetSymbolAddress((void**)&pctx, g_ctx);

    cudaFuncSetAttribute(gemm_tf32_kernel<1>,
                         cudaFuncAttributeMaxDynamicSharedMemorySize, GEMM_SMEM_BYTES);
    cudaFuncSetAttribute(gemm_tf32_kernel<0>,
                         cudaFuncAttributeMaxDynamicSharedMemorySize, GEMM_SMEM_BYTES);
    cudaFuncSetAttribute(attn_mma_kernel,
                         cudaFuncAttributeMaxDynamicSharedMemorySize, ATTN_SMEM_BYTES);

    // prep: convert x, weights to tf32 (weights Q|K|V concatenated per k-row)
    conv_flat_kernel<<<(MROWS * DD / 4 + 255) / 256, 256>>>(x, pxc, MROWS * DD / 4);
    conv_w_kernel<<<1024, 256>>>(Wq, pwqkv, 3 * DD, 0);
    conv_w_kernel<<<1024, 256>>>(Wk, pwqkv, 3 * DD, 1024);
    conv_w_kernel<<<1024, 256>>>(Wv, pwqkv, 3 * DD, 2048);
    conv_w_kernel<<<1024, 256>>>(Wo, pwo, DD, 0);

    // fused QKV projection: [8192 x 1024] * [1024 x 3072]
    dim3 qkv_grid(3 * DD / GBN, MROWS / GBM);   // (24, 64)
    gemm_tf32_kernel<1><<<qkv_grid, 128, GEMM_SMEM_BYTES>>>(
        pxc, pwqkv, bq, bk, bv, pQKV, 3 * DD);

    // attention
    dim3 attn_grid(SS / 128, HH, BB);           // (16, 16, 4)
    attn_mma_kernel<<<attn_grid, 256, ATTN_SMEM_BYTES>>>(pQKV, pctx);

    // output projection: [8192 x 1024] * [1024 x 1024] -> fp32 out
    dim3 out_grid(DD / GBN, MROWS / GBM);       // (8, 64)
    gemm_tf32_kernel<0><<<out_grid, 128, GEMM_SMEM_BYTES>>>(
        pctx, pwo, bo, bo, bo, out, DD);
}

// round 10
// speedup vs baseline: 1.8953x; 1.8953x over previous
#include <cuda_runtime.h>
#include <cuda_fp16.h>
#include <cstdint>

// Problem constants
#define BB 4
#define SS 2048
#define DD 1024
#define HH 16
#define DHD 64
#define MROWS (BB*SS)          // 8192
#define KH 1024                // K in halves (= DD)

// -------- scratch (alloc-free rule: __device__ globals) --------
__device__ __align__(128) __half g_xh[(size_t)MROWS * DD];          // x fp16
__device__ __align__(128) __half g_wqkvt[(size_t)3 * DD * DD];      // W^T qkv [n][k] fp16
__device__ __align__(128) __half g_wot[(size_t)DD * DD];            // Wo^T [n][k] fp16
__device__ __align__(128) __half g_QKV[(size_t)MROWS * 3 * DD];     // [m][3072] fp16
__device__ __align__(128) __half g_vt[(size_t)BB * HH * DHD * SS];  // V^T per (b,h): [d][s]
__device__ __align__(128) __half g_ctx[(size_t)MROWS * DD];         // fp16

// ============================================================================
// helpers
// ============================================================================
__device__ __forceinline__ void mma_f16(float* c, const uint32_t* a, const uint32_t* b) {
    asm volatile(
        "mma.sync.aligned.m16n8k16.row.col.f32.f16.f16.f32 "
        "{%0,%1,%2,%3}, {%4,%5,%6,%7}, {%8,%9}, {%0,%1,%2,%3};"
        : "+f"(c[0]), "+f"(c[1]), "+f"(c[2]), "+f"(c[3])
        : "r"(a[0]), "r"(a[1]), "r"(a[2]), "r"(a[3]), "r"(b[0]), "r"(b[1]));
}

__device__ __forceinline__ uint32_t pack_h2(float lo, float hi) {
    uint32_t r;
    asm("cvt.rn.f16x2.f32 %0, %1, %2;" : "=r"(r) : "f"(hi), "f"(lo));
    return r;
}

__device__ __forceinline__ uint32_t h2_bits(__half2 h) {
    return *reinterpret_cast<uint32_t*>(&h);
}

__device__ __forceinline__ void cp16(uint32_t dst, const void* src) {
    asm volatile("cp.async.cg.shared.global [%0], [%1], 16;" :: "r"(dst), "l"(src));
}

__device__ __forceinline__ uint32_t smem_u32(const void* p) {
    return (uint32_t)__cvta_generic_to_shared(p);
}

// ============================================================================
// prep kernels
// ============================================================================
__global__ void __launch_bounds__(256) conv_x_kernel(
    const float* __restrict__ src, __half* __restrict__ dst, int n4)
{
    int i = blockIdx.x * 256 + threadIdx.x;
    if (i >= n4) return;
    float4 v = reinterpret_cast<const float4*>(src)[i];
    uint2 o;
    o.x = pack_h2(v.x, v.y);
    o.y = pack_h2(v.z, v.w);
    reinterpret_cast<uint2*>(dst)[i] = o;
}

// W [k][n] fp32 -> Wt [coff+n][k] fp16 (k contiguous, row stride KH)
__global__ void __launch_bounds__(256) wt_kernel(
    const float* __restrict__ W, __half* __restrict__ Wt, int coff)
{
    __shared__ float tile[32][33];
    const int n0 = blockIdx.x * 32, k0 = blockIdx.y * 32;
    const int tx = threadIdx.x & 31, ty = threadIdx.x >> 5;   // 32 x 8
    #pragma unroll
    for (int i = 0; i < 4; i++)
        tile[ty + 8 * i][tx] = W[(size_t)(k0 + ty + 8 * i) * DD + n0 + tx];
    __syncthreads();
    #pragma unroll
    for (int i = 0; i < 4; i++)
        Wt[(size_t)(coff + n0 + ty + 8 * i) * KH + k0 + tx] =
            __float2half_rn(tile[tx][ty + 8 * i]);
}

// V section of QKV [s][64] -> g_vt per (b,h): [d][s]
__global__ void __launch_bounds__(256) vt_kernel(const __half* __restrict__ QKV,
                                                 __half* __restrict__ Vt)
{
    __shared__ __half sm[64 * 66];
    const int s0 = blockIdx.x * 64;
    const int h  = blockIdx.y;
    const int b  = blockIdx.z;
    const int tid = threadIdx.x;

    const __half* src = QKV + ((size_t)(b * SS + s0)) * 3072 + 2048 + h * DHD;
    #pragma unroll
    for (int p = 0; p < 8; p++) {
        int idx = tid + p * 256;              // 0..2047
        int r = idx >> 5, wd = idx & 31;      // row s, word along d
        uint32_t v = *reinterpret_cast<const uint32_t*>(src + (size_t)r * 3072 + 2 * wd);
        sm[(2 * wd) * 66 + r]     = __ushort_as_half((unsigned short)(v & 0xffff));
        sm[(2 * wd + 1) * 66 + r] = __ushort_as_half((unsigned short)(v >> 16));
    }
    __syncthreads();
    __half* dst = Vt + ((size_t)(b * HH + h)) * DHD * SS + s0;
    const uint32_t* sm32 = reinterpret_cast<const uint32_t*>(sm);
    #pragma unroll
    for (int p = 0; p < 8; p++) {
        int idx = tid + p * 256;
        int d = idx >> 5, j = idx & 31;       // row d, word along s
        *reinterpret_cast<uint32_t*>(dst + (size_t)d * SS + 2 * j) = sm32[33 * d + j];
    }
}

// ============================================================================
// fp16 mma.sync GEMM: C[m,n] = sum_k A[m,k]*Bt[n,k] + bias[n]
// A [M][KH] fp16 row-major; Bt [N][KH] fp16 (k-major). CTA 128x128, 4 warps
// of 64x64 (mt4 x nt8), m16n8k16, GBK=64 halves (32 words), double-buffered.
// OUT_F16=1 -> fp16 out (half2 stores), else fp32.
// ============================================================================
#define SA 36                        // padded row stride in words (32 data)
#define TSZ (128*SA)                 // words per tile = 4608
#define STW (2*TSZ)                  // words per stage (A+B) = 9216
#define GEMM_SMEM_BYTES (2*STW*4)    // 73728

template<int OUT_F16>
__global__ void __launch_bounds__(128, 2) gemm_f16_kernel(
    const __half* __restrict__ A, const __half* __restrict__ Bt,
    const float* __restrict__ b0, const float* __restrict__ b1,
    const float* __restrict__ b2, void* __restrict__ Cv, int N)
{
    extern __shared__ uint32_t smem[];
    const uint32_t smem_u = smem_u32(smem);

    const int tid  = threadIdx.x;
    const int wid  = tid >> 5;
    const int lane = tid & 31;
    const int g    = lane >> 2;
    const int t    = lane & 3;
    const int wm   = (wid >> 1) * 64;
    const int wn   = (wid & 1) * 64;

    const int brow = blockIdx.y * 128;
    const int bcol = blockIdx.x * 128;

    // loads: 128 rows x 8 chunks(16B) per tile; 128 threads x 8
    const int l_r = tid >> 3;            // +16/iter
    const int l_h = (tid & 7) * 8;       // half col within 64-half chunk
    const __half* Ag = A + (size_t)(brow + l_r) * KH + l_h;
    const __half* Bg = Bt + (size_t)(bcol + l_r) * KH + l_h;

    float acc[4][8][4];
    #pragma unroll
    for (int i = 0; i < 4; i++)
        #pragma unroll
        for (int j = 0; j < 8; j++)
            #pragma unroll
            for (int r = 0; r < 4; r++) acc[i][j][r] = 0.f;

    const int NIT = KH / 64;             // 16

    auto load_stage = [&](int it) {
        const int k0 = it * 64;          // halves
        const uint32_t sb = smem_u + (uint32_t)((it & 1) * STW) * 4;
        #pragma unroll
        for (int i = 0; i < 8; i++) {
            const int r = l_r + i * 16;
            const uint32_t d = (uint32_t)((r * SA + (l_h >> 1)) * 4);
            cp16(sb + d, Ag + (size_t)(i * 16) * KH + k0);
            cp16(sb + (uint32_t)(TSZ * 4) + d, Bg + (size_t)(i * 16) * KH + k0);
        }
        asm volatile("cp.async.commit_group;");
    };

    load_stage(0);

    for (int it = 0; it < NIT; ++it) {
        if (it + 1 < NIT) {
            load_stage(it + 1);
            asm volatile("cp.async.wait_group 1;");
        } else {
            asm volatile("cp.async.wait_group 0;");
        }
        __syncthreads();

        const uint32_t* As_ = smem + (it & 1) * STW;
        const uint32_t* Bs_ = As_ + TSZ;

        #pragma unroll
        for (int kk = 0; kk < 4; ++kk) {   // k16 steps: word offset 8*kk
            uint32_t af[4][4], bf[8][2];
            #pragma unroll
            for (int mt = 0; mt < 4; ++mt) {
                const uint32_t* p = As_ + (size_t)(wm + mt * 16 + g) * SA + kk * 8 + t;
                af[mt][0] = p[0];
                af[mt][1] = p[8 * SA];
                af[mt][2] = p[4];
                af[mt][3] = p[8 * SA + 4];
            }
            #pragma unroll
            for (int nt = 0; nt < 8; ++nt) {
                const uint32_t* p = Bs_ + (size_t)(wn + nt * 8 + g) * SA + kk * 8 + t;
                bf[nt][0] = p[0];
                bf[nt][1] = p[4];
            }
            #pragma unroll
            for (int mt = 0; mt < 4; ++mt)
                #pragma unroll
                for (int nt = 0; nt < 8; ++nt)
                    mma_f16(acc[mt][nt], af[mt], bf[nt]);
        }
        __syncthreads();
    }

    // epilogue (tiles never straddle 1024-col boundaries)
    const int bsel = bcol >> 10;
    const float* bias = (bsel == 0) ? b0 : (bsel == 1 ? b1 : b2);
    const int bloc = bcol & 1023;

    #pragma unroll
    for (int nt = 0; nt < 8; ++nt) {
        const int col = wn + nt * 8 + 2 * t;
        const float2 bb = *reinterpret_cast<const float2*>(&bias[bloc + col]);
        #pragma unroll
        for (int mt = 0; mt < 4; ++mt) {
            const int r0 = brow + wm + mt * 16 + g;
            float v00 = acc[mt][nt][0] + bb.x;
            float v01 = acc[mt][nt][1] + bb.y;
            float v10 = acc[mt][nt][2] + bb.x;
            float v11 = acc[mt][nt][3] + bb.y;
            if (OUT_F16) {
                __half* C = (__half*)Cv;
                *reinterpret_cast<uint32_t*>(&C[(size_t)r0 * N + bcol + col]) = pack_h2(v00, v01);
                *reinterpret_cast<uint32_t*>(&C[(size_t)(r0 + 8) * N + bcol + col]) = pack_h2(v10, v11);
            } else {
                float* C = (float*)Cv;
                float2 o0; o0.x = v00; o0.y = v01;
                float2 o1; o1.x = v10; o1.y = v11;
                *reinterpret_cast<float2*>(&C[(size_t)r0 * N + bcol + col]) = o0;
                *reinterpret_cast<float2*>(&C[(size_t)(r0 + 8) * N + bcol + col]) = o1;
            }
        }
    }
}

// ============================================================================
// Causal flash attention, fp16 m16n8k16.
// 256 thr, 128 q rows/block; warp w owns q [16w,16w+16). S = Q*K^T computed
// non-transposed (A=Q regs, B=K smem natural); softmax over n-dim via t-lane
// shuffles; P feeds P*V A-frags DIRECTLY from registers; V^T tiles in smem.
// Double-buffered K/V^T tile pipeline via cp.async.
// ============================================================================
#define AKS 36                        // K/Vt tile row stride (words)
#define ATSZ (64*AKS)                 // 2304 words per tile
#define ASTW (2*ATSZ)                 // per stage (K+Vt) = 4608 words
#define ATTN_SMEM_BYTES (2*ASTW*4)    // 36864

__global__ void __launch_bounds__(256, 2) attn_f16_kernel(
    const __half* __restrict__ QKV, const __half* __restrict__ VtG,
    __half* __restrict__ Ctx)
{
    extern __shared__ uint32_t sm[];
    const uint32_t smb = smem_u32(sm);

    const int qblk = gridDim.x - 1 - blockIdx.x;   // high-work blocks first
    const int h    = blockIdx.y;
    const int b    = blockIdx.z;
    const int tid  = threadIdx.x;
    const int w    = tid >> 5;
    const int lane = tid & 31;
    const int g    = lane >> 2;
    const int t    = lane & 3;
    const int q0   = qblk * 128;

    const __half* Qg  = QKV + ((size_t)(b * SS + q0)) * 3072 + h * DHD;
    const __half* Kg  = QKV + ((size_t)(b * SS)) * 3072 + 1024 + h * DHD;
    const __half* Vtg = VtG + ((size_t)(b * HH + h)) * DHD * SS;

    // ---- Q A-fragments into registers (scale 0.125 folded) ----
    uint32_t qf[4][4];
    {
        const __half2 sc2 = __float2half2_rn(0.125f);
        const __half* qr0 = Qg + (size_t)(w * 16 + g) * 3072;
        const __half* qr8 = qr0 + (size_t)8 * 3072;
        #pragma unroll
        for (int kk = 0; kk < 4; kk++) {
            __half2 a0 = *reinterpret_cast<const __half2*>(qr0 + kk * 16 + 2 * t);
            __half2 a1 = *reinterpret_cast<const __half2*>(qr8 + kk * 16 + 2 * t);
            __half2 a2 = *reinterpret_cast<const __half2*>(qr0 + kk * 16 + 8 + 2 * t);
            __half2 a3 = *reinterpret_cast<const __half2*>(qr8 + kk * 16 + 8 + 2 * t);
            __half2 m0 = __hmul2(a0, sc2);
            __half2 m1 = __hmul2(a1, sc2);
            __half2 m2 = __hmul2(a2, sc2);
            __half2 m3 = __hmul2(a3, sc2);
            qf[kk][0] = h2_bits(m0);
            qf[kk][1] = h2_bits(m1);
            qf[kk][2] = h2_bits(m2);
            qf[kk][3] = h2_bits(m3);
        }
    }

    float m0 = -1e30f, m1 = -1e30f, l0 = 0.f, l1 = 0.f;
    float oc[8][4];
    #pragma unroll
    for (int nt = 0; nt < 8; nt++)
        #pragma unroll
        for (int r = 0; r < 4; r++) oc[nt][r] = 0.f;

    // tile loads: 64 rows x 8 chunks(16B); 256 threads x 2
    const int l_r = tid >> 3;            // +32/iter
    const int l_h = (tid & 7) * 8;

    auto load_tile = [&](int tt) {
        const int kv0 = tt * 64;
        const uint32_t sb = smb + (uint32_t)((tt & 1) * ASTW) * 4;
        #pragma unroll
        for (int i = 0; i < 2; i++) {
            const int r = l_r + i * 32;
            const uint32_t d = (uint32_t)((r * AKS + (l_h >> 1)) * 4);
            cp16(sb + d, Kg + (size_t)(kv0 + r) * 3072 + l_h);
            cp16(sb + (uint32_t)(ATSZ * 4) + d, Vtg + (size_t)r * SS + kv0 + l_h);
        }
        asm volatile("cp.async.commit_group;");
    };

    const int ntiles = 2 * qblk + 2;
    load_tile(0);

    for (int tt = 0; tt < ntiles; tt++) {
        if (tt + 1 < ntiles) {
            load_tile(tt + 1);
            asm volatile("cp.async.wait_group 1;");
        } else {
            asm volatile("cp.async.wait_group 0;");
        }
        __syncthreads();

        const uint32_t* Ks = sm + (tt & 1) * ASTW;
        const uint32_t* Vs = Ks + ATSZ;

        // ---- S[q][kv] = Q*K^T : 4 kk(d16) x 8 nt(kv8) ----
        float sc[8][4];
        #pragma unroll
        for (int nt = 0; nt < 8; nt++)
            #pragma unroll
            for (int r = 0; r < 4; r++) sc[nt][r] = 0.f;

        #pragma unroll
        for (int kk = 0; kk < 4; kk++) {
            #pragma unroll
            for (int nt = 0; nt < 8; nt++) {
                uint32_t bf[2];
                const uint32_t* p = Ks + (size_t)(nt * 8 + g) * AKS + kk * 8 + t;
                bf[0] = p[0];
                bf[1] = p[4];
                mma_f16(sc[nt], qf[kk], bf);
            }
        }

        // ---- causal mask (last two tiles only) ----
        if (tt >= 2 * qblk) {
            const int kvb = tt * 64;
            const int qg0 = q0 + w * 16 + g;
            #pragma unroll
            for (int nt = 0; nt < 8; nt++)
                #pragma unroll
                for (int c = 0; c < 2; c++) {
                    const int kv = kvb + nt * 8 + 2 * t + c;
                    if (kv > qg0)     sc[nt][c]     = -1e30f;
                    if (kv > qg0 + 8) sc[nt][2 + c] = -1e30f;
                }
        }

        // ---- online softmax over kv (n-dim): reduce over t lanes ----
        float tmax0 = -1e30f, tmax1 = -1e30f;
        #pragma unroll
        for (int nt = 0; nt < 8; nt++) {
            tmax0 = fmaxf(tmax0, fmaxf(sc[nt][0], sc[nt][1]));
            tmax1 = fmaxf(tmax1, fmaxf(sc[nt][2], sc[nt][3]));
        }
        tmax0 = fmaxf(tmax0, __shfl_xor_sync(0xffffffffu, tmax0, 1));
        tmax0 = fmaxf(tmax0, __shfl_xor_sync(0xffffffffu, tmax0, 2));
        tmax1 = fmaxf(tmax1, __shfl_xor_sync(0xffffffffu, tmax1, 1));
        tmax1 = fmaxf(tmax1, __shfl_xor_sync(0xffffffffu, tmax1, 2));

        const float mn0 = fmaxf(m0, tmax0);
        const float mn1 = fmaxf(m1, tmax1);
        const float cr0 = __expf(m0 - mn0);
        const float cr1 = __expf(m1 - mn1);
        m0 = mn0; m1 = mn1;

        float ts0 = 0.f, ts1 = 0.f;
        #pragma unroll
        for (int nt = 0; nt < 8; nt++) {
            sc[nt][0] = __expf(sc[nt][0] - mn0);
            sc[nt][1] = __expf(sc[nt][1] - mn0);
            sc[nt][2] = __expf(sc[nt][2] - mn1);
            sc[nt][3] = __expf(sc[nt][3] - mn1);
            ts0 += sc[nt][0] + sc[nt][1];
            ts1 += sc[nt][2] + sc[nt][3];
        }
        ts0 += __shfl_xor_sync(0xffffffffu, ts0, 1);
        ts0 += __shfl_xor_sync(0xffffffffu, ts0, 2);
        ts1 += __shfl_xor_sync(0xffffffffu, ts1, 1);
        ts1 += __shfl_xor_sync(0xffffffffu, ts1, 2);
        l0 = l0 * cr0 + ts0;
        l1 = l1 * cr1 + ts1;

        #pragma unroll
        for (int nt = 0; nt < 8; nt++) {
            oc[nt][0] *= cr0; oc[nt][1] *= cr0;
            oc[nt][2] *= cr1; oc[nt][3] *= cr1;
        }

        // ---- O += P*V : P A-frags straight from sc registers ----
        #pragma unroll
        for (int kk = 0; kk < 4; kk++) {   // kv16 chunks
            uint32_t af[4];
            af[0] = pack_h2(sc[2 * kk][0],     sc[2 * kk][1]);
            af[1] = pack_h2(sc[2 * kk][2],     sc[2 * kk][3]);
            af[2] = pack_h2(sc[2 * kk + 1][0], sc[2 * kk + 1][1]);
            af[3] = pack_h2(sc[2 * kk + 1][2], sc[2 * kk + 1][3]);
            #pragma unroll
            for (int nt = 0; nt < 8; nt++) {
                uint32_t bf[2];
                const uint32_t* p = Vs + (size_t)(nt * 8 + g) * AKS + kk * 8 + t;
                bf[0] = p[0];
                bf[1] = p[4];
                mma_f16(oc[nt], af, bf);
            }
        }
        __syncthreads();
    }

    // ---- epilogue ----
    const float li0 = 1.f / l0;
    const float li1 = 1.f / l1;
    __half* Og = Ctx + ((size_t)(b * SS + q0 + w * 16)) * DD + h * DHD;
    #pragma unroll
    for (int nt = 0; nt < 8; nt++) {
        const int col = nt * 8 + 2 * t;
        *reinterpret_cast<uint32_t*>(Og + (size_t)g * DD + col) =
            pack_h2(oc[nt][0] * li0, oc[nt][1] * li0);
        *reinterpret_cast<uint32_t*>(Og + (size_t)(g + 8) * DD + col) =
            pack_h2(oc[nt][2] * li1, oc[nt][3] * li1);
    }
}

// ============================================================================
// launch
// ============================================================================
extern "C" void kernel_launch(void* const* d_in, const int* in_sizes, int n_in,
                              void* d_out, int out_size)
{
    const float* x  = (const float*)d_in[0];
    const float* Wq = (const float*)d_in[1];
    const float* bq = (const float*)d_in[2];
    const float* Wk = (const float*)d_in[3];
    const float* bk = (const float*)d_in[4];
    const float* Wv = (const float*)d_in[5];
    const float* bv = (const float*)d_in[6];
    const float* Wo = (const float*)d_in[7];
    const float* bo = (const float*)d_in[8];
    float* out = (float*)d_out;

    __half *pxh, *pwqkvt, *pwot, *pQKV, *pvt, *pctx;
    cudaGetSymbolAddress((void**)&pxh, g_xh);
    cudaGetSymbolAddress((void**)&pwqkvt, g_wqkvt);
    cudaGetSymbolAddress((void**)&pwot, g_wot);
    cudaGetSymbolAddress((void**)&pQKV, g_QKV);
    cudaGetSymbolAddress((void**)&pvt, g_vt);
    cudaGetSymbolAddress((void**)&pctx, g_ctx);

    cudaFuncSetAttribute(gemm_f16_kernel<1>,
                         cudaFuncAttributeMaxDynamicSharedMemorySize, GEMM_SMEM_BYTES);
    cudaFuncSetAttribute(gemm_f16_kernel<0>,
                         cudaFuncAttributeMaxDynamicSharedMemorySize, GEMM_SMEM_BYTES);
    cudaFuncSetAttribute(attn_f16_kernel,
                         cudaFuncAttributeMaxDynamicSharedMemorySize, ATTN_SMEM_BYTES);

    // prep
    conv_x_kernel<<<(MROWS * DD / 4 + 255) / 256, 256>>>(x, pxh, MROWS * DD / 4);
    dim3 wgrid(32, 32);
    wt_kernel<<<wgrid, 256>>>(Wq, pwqkvt, 0);
    wt_kernel<<<wgrid, 256>>>(Wk, pwqkvt, 1024);
    wt_kernel<<<wgrid, 256>>>(Wv, pwqkvt, 2048);
    wt_kernel<<<wgrid, 256>>>(Wo, pwot, 0);

    // fused QKV projection (fp16 out)
    dim3 qkv_grid(3 * DD / 128, MROWS / 128);   // (24, 64)
    gemm_f16_kernel<1><<<qkv_grid, 128, GEMM_SMEM_BYTES>>>(
        pxh, pwqkvt, bq, bk, bv, pQKV, 3 * DD);

    // V transpose per (b,h)
    dim3 vt_grid(SS / 64, HH, BB);
    vt_kernel<<<vt_grid, 256>>>(pQKV, pvt);

    // attention
    dim3 attn_grid(SS / 128, HH, BB);           // (16, 16, 4)
    attn_f16_kernel<<<attn_grid, 256, ATTN_SMEM_BYTES>>>(pQKV, pvt, pctx);

    // output projection (fp32 out)
    dim3 out_grid(DD / 128, MROWS / 128);       // (8, 64)
    gemm_f16_kernel<0><<<out_grid, 128, GEMM_SMEM_BYTES>>>(
        pctx, pwot, bo, bo, bo, out, DD);
}

// round 11
// speedup vs baseline: 1.9913x; 1.0507x over previous
#include <cuda_runtime.h>
#include <cuda_fp16.h>
#include <cstdint>

// Problem constants
#define BB 4
#define SS 2048
#define DD 1024
#define HH 16
#define DHD 64
#define MROWS (BB*SS)          // 8192
#define KH 1024                // K in halves (= DD)

// -------- scratch (alloc-free rule: __device__ globals) --------
__device__ __align__(128) __half g_xh[(size_t)MROWS * DD];          // x fp16
__device__ __align__(128) __half g_wqkvt[(size_t)3 * DD * DD];      // W^T qkv [n][k] fp16
__device__ __align__(128) __half g_wot[(size_t)DD * DD];            // Wo^T [n][k] fp16
__device__ __align__(128) __half g_QKV[(size_t)MROWS * 3 * DD];     // [m][3072] fp16
__device__ __align__(128) __half g_vt[(size_t)BB * HH * DHD * SS];  // V^T per (b,h): [d][s]
__device__ __align__(128) __half g_ctx[(size_t)MROWS * DD];         // fp16

// ============================================================================
// helpers
// ============================================================================
__device__ __forceinline__ void mma_f16(float* c, const uint32_t* a, const uint32_t* b) {
    asm volatile(
        "mma.sync.aligned.m16n8k16.row.col.f32.f16.f16.f32 "
        "{%0,%1,%2,%3}, {%4,%5,%6,%7}, {%8,%9}, {%0,%1,%2,%3};"
        : "+f"(c[0]), "+f"(c[1]), "+f"(c[2]), "+f"(c[3])
        : "r"(a[0]), "r"(a[1]), "r"(a[2]), "r"(a[3]), "r"(b[0]), "r"(b[1]));
}

__device__ __forceinline__ void ldsm_x4(uint32_t& r0, uint32_t& r1,
                                        uint32_t& r2, uint32_t& r3, uint32_t addr) {
    asm volatile("ldmatrix.sync.aligned.m8n8.x4.shared.b16 {%0,%1,%2,%3}, [%4];"
        : "=r"(r0), "=r"(r1), "=r"(r2), "=r"(r3) : "r"(addr));
}

__device__ __forceinline__ uint32_t pack_h2(float lo, float hi) {
    uint32_t r;
    asm("cvt.rn.f16x2.f32 %0, %1, %2;" : "=r"(r) : "f"(hi), "f"(lo));
    return r;
}

__device__ __forceinline__ uint32_t h2_bits(__half2 h) {
    return *reinterpret_cast<uint32_t*>(&h);
}

__device__ __forceinline__ void cp16(uint32_t dst, const void* src) {
    asm volatile("cp.async.cg.shared.global [%0], [%1], 16;" :: "r"(dst), "l"(src));
}

__device__ __forceinline__ uint32_t smem_u32(const void* p) {
    return (uint32_t)__cvta_generic_to_shared(p);
}

// ============================================================================
// prep kernels
// ============================================================================
__global__ void __launch_bounds__(256) conv_x_kernel(
    const float* __restrict__ src, __half* __restrict__ dst, int n4)
{
    int i = blockIdx.x * 256 + threadIdx.x;
    if (i >= n4) return;
    float4 v = reinterpret_cast<const float4*>(src)[i];
    uint2 o;
    o.x = pack_h2(v.x, v.y);
    o.y = pack_h2(v.z, v.w);
    reinterpret_cast<uint2*>(dst)[i] = o;
}

// all 4 weights in one launch: W [k][n] fp32 -> Wt [n][k] fp16
__global__ void __launch_bounds__(256) wt_all_kernel(
    const float* __restrict__ Wq, const float* __restrict__ Wk,
    const float* __restrict__ Wv, const float* __restrict__ Wo,
    __half* __restrict__ Wqkvt, __half* __restrict__ Wot)
{
    __shared__ float tile[32][33];
    const int sel = blockIdx.z;
    const float* W = (sel == 0) ? Wq : (sel == 1) ? Wk : (sel == 2) ? Wv : Wo;
    __half* Wt = (sel < 3) ? (Wqkvt + (size_t)sel * DD * KH) : Wot;

    const int n0 = blockIdx.x * 32, k0 = blockIdx.y * 32;
    const int tx = threadIdx.x & 31, ty = threadIdx.x >> 5;   // 32 x 8
    #pragma unroll
    for (int i = 0; i < 4; i++)
        tile[ty + 8 * i][tx] = W[(size_t)(k0 + ty + 8 * i) * DD + n0 + tx];
    __syncthreads();
    #pragma unroll
    for (int i = 0; i < 4; i++)
        Wt[(size_t)(n0 + ty + 8 * i) * KH + k0 + tx] =
            __float2half_rn(tile[tx][ty + 8 * i]);
}

// V section of QKV [s][64] -> g_vt per (b,h): [d][s]
__global__ void __launch_bounds__(256) vt_kernel(const __half* __restrict__ QKV,
                                                 __half* __restrict__ Vt)
{
    __shared__ __half sm[64 * 66];
    const int s0 = blockIdx.x * 64;
    const int h  = blockIdx.y;
    const int b  = blockIdx.z;
    const int tid = threadIdx.x;

    const __half* src = QKV + ((size_t)(b * SS + s0)) * 3072 + 2048 + h * DHD;
    #pragma unroll
    for (int p = 0; p < 8; p++) {
        int idx = tid + p * 256;              // 0..2047
        int r = idx >> 5, wd = idx & 31;      // row s, word along d
        uint32_t v = *reinterpret_cast<const uint32_t*>(src + (size_t)r * 3072 + 2 * wd);
        sm[(2 * wd) * 66 + r]     = __ushort_as_half((unsigned short)(v & 0xffff));
        sm[(2 * wd + 1) * 66 + r] = __ushort_as_half((unsigned short)(v >> 16));
    }
    __syncthreads();
    __half* dst = Vt + ((size_t)(b * HH + h)) * DHD * SS + s0;
    const uint32_t* sm32 = reinterpret_cast<const uint32_t*>(sm);
    #pragma unroll
    for (int p = 0; p < 8; p++) {
        int idx = tid + p * 256;
        int d = idx >> 5, j = idx & 31;       // row d, word along s
        *reinterpret_cast<uint32_t*>(dst + (size_t)d * SS + 2 * j) = sm32[33 * d + j];
    }
}

// ============================================================================
// fp16 mma.sync GEMM with ldmatrix fragment loads.
// C[m,n] = sum_k A[m,k]*Bt[n,k] + bias[n]; CTA 128x128, 4 warps of 64x64,
// m16n8k16, GBK=64 halves, double-buffered cp.async.
// ============================================================================
#define SA 36                        // padded row stride in words (32 data)
#define TSZ (128*SA)                 // words per tile = 4608
#define STW (2*TSZ)                  // words per stage (A+B) = 9216
#define GEMM_SMEM_BYTES (2*STW*4)    // 73728

template<int OUT_F16>
__global__ void __launch_bounds__(128, 2) gemm_f16_kernel(
    const __half* __restrict__ A, const __half* __restrict__ Bt,
    const float* __restrict__ b0, const float* __restrict__ b1,
    const float* __restrict__ b2, void* __restrict__ Cv, int N)
{
    extern __shared__ uint32_t smem[];
    const uint32_t smem_u = smem_u32(smem);

    const int tid  = threadIdx.x;
    const int wid  = tid >> 5;
    const int lane = tid & 31;
    const int t    = lane & 3;
    const int g    = lane >> 2;
    const int wm   = (wid >> 1) * 64;
    const int wn   = (wid & 1) * 64;

    // ldmatrix lane address components
    const int aRowL = wm + (lane & 15);          // + mt*16
    const int aColW = (lane >> 4) * 4;           // + kk*8
    const int bRowL = wn + ((lane >> 4) << 3) + (lane & 7);   // + np*16
    const int bColW = ((lane >> 3) & 1) * 4;     // + kk*8

    const int brow = blockIdx.y * 128;
    const int bcol = blockIdx.x * 128;

    // loads: 128 rows x 8 chunks(16B) per tile; 128 threads x 8
    const int l_r = tid >> 3;            // +16/iter
    const int l_h = (tid & 7) * 8;       // half col within 64-half chunk
    const __half* Ag = A + (size_t)(brow + l_r) * KH + l_h;
    const __half* Bg = Bt + (size_t)(bcol + l_r) * KH + l_h;

    float acc[4][8][4];
    #pragma unroll
    for (int i = 0; i < 4; i++)
        #pragma unroll
        for (int j = 0; j < 8; j++)
            #pragma unroll
            for (int r = 0; r < 4; r++) acc[i][j][r] = 0.f;

    const int NIT = KH / 64;             // 16

    auto load_stage = [&](int it) {
        const int k0 = it * 64;          // halves
        const uint32_t sb = smem_u + (uint32_t)((it & 1) * STW) * 4;
        #pragma unroll
        for (int i = 0; i < 8; i++) {
            const int r = l_r + i * 16;
            const uint32_t d = (uint32_t)((r * SA + (l_h >> 1)) * 4);
            cp16(sb + d, Ag + (size_t)(i * 16) * KH + k0);
            cp16(sb + (uint32_t)(TSZ * 4) + d, Bg + (size_t)(i * 16) * KH + k0);
        }
        asm volatile("cp.async.commit_group;");
    };

    load_stage(0);

    for (int it = 0; it < NIT; ++it) {
        if (it + 1 < NIT) {
            load_stage(it + 1);
            asm volatile("cp.async.wait_group 1;");
        } else {
            asm volatile("cp.async.wait_group 0;");
        }
        __syncthreads();

        const uint32_t asb = smem_u + (uint32_t)((it & 1) * STW) * 4;
        const uint32_t bsb = asb + (uint32_t)(TSZ * 4);

        #pragma unroll
        for (int kk = 0; kk < 4; ++kk) {   // k16 steps
            uint32_t af[4][4], bf[8][2];
            #pragma unroll
            for (int mt = 0; mt < 4; ++mt)
                ldsm_x4(af[mt][0], af[mt][1], af[mt][2], af[mt][3],
                        asb + (uint32_t)(((aRowL + mt * 16) * SA + kk * 8 + aColW) * 4));
            #pragma unroll
            for (int np = 0; np < 4; ++np) {
                uint32_t r0, r1, r2, r3;
                ldsm_x4(r0, r1, r2, r3,
                        bsb + (uint32_t)(((bRowL + np * 16) * SA + kk * 8 + bColW) * 4));
                bf[2 * np][0] = r0;     bf[2 * np][1] = r1;
                bf[2 * np + 1][0] = r2; bf[2 * np + 1][1] = r3;
            }
            #pragma unroll
            for (int mt = 0; mt < 4; ++mt)
                #pragma unroll
                for (int nt = 0; nt < 8; ++nt)
                    mma_f16(acc[mt][nt], af[mt], bf[nt]);
        }
        __syncthreads();
    }

    // epilogue (tiles never straddle 1024-col boundaries)
    const int bsel = bcol >> 10;
    const float* bias = (bsel == 0) ? b0 : (bsel == 1 ? b1 : b2);
    const int bloc = bcol & 1023;

    #pragma unroll
    for (int nt = 0; nt < 8; ++nt) {
        const int col = wn + nt * 8 + 2 * t;
        const float2 bb = *reinterpret_cast<const float2*>(&bias[bloc + col]);
        #pragma unroll
        for (int mt = 0; mt < 4; ++mt) {
            const int r0 = brow + wm + mt * 16 + g;
            float v00 = acc[mt][nt][0] + bb.x;
            float v01 = acc[mt][nt][1] + bb.y;
            float v10 = acc[mt][nt][2] + bb.x;
            float v11 = acc[mt][nt][3] + bb.y;
            if (OUT_F16) {
                __half* C = (__half*)Cv;
                *reinterpret_cast<uint32_t*>(&C[(size_t)r0 * N + bcol + col]) = pack_h2(v00, v01);
                *reinterpret_cast<uint32_t*>(&C[(size_t)(r0 + 8) * N + bcol + col]) = pack_h2(v10, v11);
            } else {
                float* C = (float*)Cv;
                float2 o0; o0.x = v00; o0.y = v01;
                float2 o1; o1.x = v10; o1.y = v11;
                *reinterpret_cast<float2*>(&C[(size_t)r0 * N + bcol + col]) = o0;
                *reinterpret_cast<float2*>(&C[(size_t)(r0 + 8) * N + bcol + col]) = o1;
            }
        }
    }
}

// ============================================================================
// Causal flash attention, fp16 m16n8k16 with ldmatrix B-fragment loads.
// 256 thr, 128 q rows/block; S = Q*K^T (A=Q regs, B=K smem natural);
// softmax over n-dim via t-lane shuffles; P feeds P*V directly from regs;
// V^T tiles in smem. Double-buffered K/V^T via cp.async.
// ============================================================================
#define AKS 36                        // K/Vt tile row stride (words)
#define ATSZ (64*AKS)                 // 2304 words per tile
#define ASTW (2*ATSZ)                 // per stage (K+Vt) = 4608 words
#define ATTN_SMEM_BYTES (2*ASTW*4)    // 36864

__global__ void __launch_bounds__(256, 2) attn_f16_kernel(
    const __half* __restrict__ QKV, const __half* __restrict__ VtG,
    __half* __restrict__ Ctx)
{
    extern __shared__ uint32_t sm[];
    const uint32_t smb = smem_u32(sm);

    const int qblk = gridDim.x - 1 - blockIdx.x;   // high-work blocks first
    const int h    = blockIdx.y;
    const int b    = blockIdx.z;
    const int tid  = threadIdx.x;
    const int w    = tid >> 5;
    const int lane = tid & 31;
    const int g    = lane >> 2;
    const int t    = lane & 3;
    const int q0   = qblk * 128;

    // ldmatrix lane address components (B pattern)
    const int bRowL = ((lane >> 4) << 3) + (lane & 7);        // + np*16
    const int bColW = ((lane >> 3) & 1) * 4;                  // + kk*8

    const __half* Qg  = QKV + ((size_t)(b * SS + q0)) * 3072 + h * DHD;
    const __half* Kg  = QKV + ((size_t)(b * SS)) * 3072 + 1024 + h * DHD;
    const __half* Vtg = VtG + ((size_t)(b * HH + h)) * DHD * SS;

    // ---- Q A-fragments into registers (scale 0.125 folded) ----
    uint32_t qf[4][4];
    {
        const __half2 sc2 = __float2half2_rn(0.125f);
        const __half* qr0 = Qg + (size_t)(w * 16 + g) * 3072;
        const __half* qr8 = qr0 + (size_t)8 * 3072;
        #pragma unroll
        for (int kk = 0; kk < 4; kk++) {
            __half2 a0 = *reinterpret_cast<const __half2*>(qr0 + kk * 16 + 2 * t);
            __half2 a1 = *reinterpret_cast<const __half2*>(qr8 + kk * 16 + 2 * t);
            __half2 a2 = *reinterpret_cast<const __half2*>(qr0 + kk * 16 + 8 + 2 * t);
            __half2 a3 = *reinterpret_cast<const __half2*>(qr8 + kk * 16 + 8 + 2 * t);
            __half2 p0 = __hmul2(a0, sc2);
            __half2 p1 = __hmul2(a1, sc2);
            __half2 p2 = __hmul2(a2, sc2);
            __half2 p3 = __hmul2(a3, sc2);
            qf[kk][0] = h2_bits(p0);
            qf[kk][1] = h2_bits(p1);
            qf[kk][2] = h2_bits(p2);
            qf[kk][3] = h2_bits(p3);
        }
    }

    float m0 = -1e30f, m1 = -1e30f, l0 = 0.f, l1 = 0.f;
    float oc[8][4];
    #pragma unroll
    for (int nt = 0; nt < 8; nt++)
        #pragma unroll
        for (int r = 0; r < 4; r++) oc[nt][r] = 0.f;

    // tile loads: 64 rows x 8 chunks(16B); 256 threads x 2
    const int l_r = tid >> 3;            // +32/iter
    const int l_h = (tid & 7) * 8;

    auto load_tile = [&](int tt) {
        const int kv0 = tt * 64;
        const uint32_t sb = smb + (uint32_t)((tt & 1) * ASTW) * 4;
        #pragma unroll
        for (int i = 0; i < 2; i++) {
            const int r = l_r + i * 32;
            const uint32_t d = (uint32_t)((r * AKS + (l_h >> 1)) * 4);
            cp16(sb + d, Kg + (size_t)(kv0 + r) * 3072 + l_h);
            cp16(sb + (uint32_t)(ATSZ * 4) + d, Vtg + (size_t)r * SS + kv0 + l_h);
        }
        asm volatile("cp.async.commit_group;");
    };

    const int ntiles = 2 * qblk + 2;
    load_tile(0);

    for (int tt = 0; tt < ntiles; tt++) {
        if (tt + 1 < ntiles) {
            load_tile(tt + 1);
            asm volatile("cp.async.wait_group 1;");
        } else {
            asm volatile("cp.async.wait_group 0;");
        }
        __syncthreads();

        const uint32_t ksb = smb + (uint32_t)((tt & 1) * ASTW) * 4;
        const uint32_t vsb = ksb + (uint32_t)(ATSZ * 4);

        // ---- S[q][kv] = Q*K^T ----
        float sc[8][4];
        #pragma unroll
        for (int nt = 0; nt < 8; nt++)
            #pragma unroll
            for (int r = 0; r < 4; r++) sc[nt][r] = 0.f;

        #pragma unroll
        for (int kk = 0; kk < 4; kk++) {
            uint32_t bf[8][2];
            #pragma unroll
            for (int np = 0; np < 4; np++) {
                uint32_t r0, r1, r2, r3;
                ldsm_x4(r0, r1, r2, r3,
                        ksb + (uint32_t)(((bRowL + np * 16) * AKS + kk * 8 + bColW) * 4));
                bf[2 * np][0] = r0;     bf[2 * np][1] = r1;
                bf[2 * np + 1][0] = r2; bf[2 * np + 1][1] = r3;
            }
            #pragma unroll
            for (int nt = 0; nt < 8; nt++)
                mma_f16(sc[nt], qf[kk], bf[nt]);
        }

        // ---- causal mask (last two tiles only) ----
        if (tt >= 2 * qblk) {
            const int kvb = tt * 64;
            const int qg0 = q0 + w * 16 + g;
            #pragma unroll
            for (int nt = 0; nt < 8; nt++)
                #pragma unroll
                for (int c = 0; c < 2; c++) {
                    const int kv = kvb + nt * 8 + 2 * t + c;
                    if (kv > qg0)     sc[nt][c]     = -1e30f;
                    if (kv > qg0 + 8) sc[nt][2 + c] = -1e30f;
                }
        }

        // ---- online softmax over kv (n-dim): reduce over t lanes ----
        float tmax0 = -1e30f, tmax1 = -1e30f;
        #pragma unroll
        for (int nt = 0; nt < 8; nt++) {
            tmax0 = fmaxf(tmax0, fmaxf(sc[nt][0], sc[nt][1]));
            tmax1 = fmaxf(tmax1, fmaxf(sc[nt][2], sc[nt][3]));
        }
        tmax0 = fmaxf(tmax0, __shfl_xor_sync(0xffffffffu, tmax0, 1));
        tmax0 = fmaxf(tmax0, __shfl_xor_sync(0xffffffffu, tmax0, 2));
        tmax1 = fmaxf(tmax1, __shfl_xor_sync(0xffffffffu, tmax1, 1));
        tmax1 = fmaxf(tmax1, __shfl_xor_sync(0xffffffffu, tmax1, 2));

        const float mn0 = fmaxf(m0, tmax0);
        const float mn1 = fmaxf(m1, tmax1);
        const float cr0 = __expf(m0 - mn0);
        const float cr1 = __expf(m1 - mn1);
        m0 = mn0; m1 = mn1;

        float ts0 = 0.f, ts1 = 0.f;
        #pragma unroll
        for (int nt = 0; nt < 8; nt++) {
            sc[nt][0] = __expf(sc[nt][0] - mn0);
            sc[nt][1] = __expf(sc[nt][1] - mn0);
            sc[nt][2] = __expf(sc[nt][2] - mn1);
            sc[nt][3] = __expf(sc[nt][3] - mn1);
            ts0 += sc[nt][0] + sc[nt][1];
            ts1 += sc[nt][2] + sc[nt][3];
        }
        ts0 += __shfl_xor_sync(0xffffffffu, ts0, 1);
        ts0 += __shfl_xor_sync(0xffffffffu, ts0, 2);
        ts1 += __shfl_xor_sync(0xffffffffu, ts1, 1);
        ts1 += __shfl_xor_sync(0xffffffffu, ts1, 2);
        l0 = l0 * cr0 + ts0;
        l1 = l1 * cr1 + ts1;

        #pragma unroll
        for (int nt = 0; nt < 8; nt++) {
            oc[nt][0] *= cr0; oc[nt][1] *= cr0;
            oc[nt][2] *= cr1; oc[nt][3] *= cr1;
        }

        // ---- O += P*V : P A-frags straight from sc registers ----
        #pragma unroll
        for (int kk = 0; kk < 4; kk++) {   // kv16 chunks
            uint32_t af[4];
            af[0] = pack_h2(sc[2 * kk][0],     sc[2 * kk][1]);
            af[1] = pack_h2(sc[2 * kk][2],     sc[2 * kk][3]);
            af[2] = pack_h2(sc[2 * kk + 1][0], sc[2 * kk + 1][1]);
            af[3] = pack_h2(sc[2 * kk + 1][2], sc[2 * kk + 1][3]);
            uint32_t bf[8][2];
            #pragma unroll
            for (int np = 0; np < 4; np++) {
                uint32_t r0, r1, r2, r3;
                ldsm_x4(r0, r1, r2, r3,
                        vsb + (uint32_t)(((bRowL + np * 16) * AKS + kk * 8 + bColW) * 4));
                bf[2 * np][0] = r0;     bf[2 * np][1] = r1;
                bf[2 * np + 1][0] = r2; bf[2 * np + 1][1] = r3;
            }
            #pragma unroll
            for (int nt = 0; nt < 8; nt++)
                mma_f16(oc[nt], af, bf[nt]);
        }
        __syncthreads();
    }

    // ---- epilogue ----
    const float li0 = 1.f / l0;
    const float li1 = 1.f / l1;
    __half* Og = Ctx + ((size_t)(b * SS + q0 + w * 16)) * DD + h * DHD;
    #pragma unroll
    for (int nt = 0; nt < 8; nt++) {
        const int col = nt * 8 + 2 * t;
        *reinterpret_cast<uint32_t*>(Og + (size_t)g * DD + col) =
            pack_h2(oc[nt][0] * li0, oc[nt][1] * li0);
        *reinterpret_cast<uint32_t*>(Og + (size_t)(g + 8) * DD + col) =
            pack_h2(oc[nt][2] * li1, oc[nt][3] * li1);
    }
}

// ============================================================================
// launch
// ============================================================================
extern "C" void kernel_launch(void* const* d_in, const int* in_sizes, int n_in,
                              void* d_out, int out_size)
{
    const float* x  = (const float*)d_in[0];
    const float* Wq = (const float*)d_in[1];
    const float* bq = (const float*)d_in[2];
    const float* Wk = (const float*)d_in[3];
    const float* bk = (const float*)d_in[4];
    const float* Wv = (const float*)d_in[5];
    const float* bv = (const float*)d_in[6];
    const float* Wo = (const float*)d_in[7];
    const float* bo = (const float*)d_in[8];
    float* out = (float*)d_out;

    __half *pxh, *pwqkvt, *pwot, *pQKV, *pvt, *pctx;
    cudaGetSymbolAddress((void**)&pxh, g_xh);
    cudaGetSymbolAddress((void**)&pwqkvt, g_wqkvt);
    cudaGetSymbolAddress((void**)&pwot, g_wot);
    cudaGetSymbolAddress((void**)&pQKV, g_QKV);
    cudaGetSymbolAddress((void**)&pvt, g_vt);
    cudaGetSymbolAddress((void**)&pctx, g_ctx);

    cudaFuncSetAttribute(gemm_f16_kernel<1>,
                         cudaFuncAttributeMaxDynamicSharedMemorySize, GEMM_SMEM_BYTES);
    cudaFuncSetAttribute(gemm_f16_kernel<0>,
                         cudaFuncAttributeMaxDynamicSharedMemorySize, GEMM_SMEM_BYTES);
    cudaFuncSetAttribute(attn_f16_kernel,
                         cudaFuncAttributeMaxDynamicSharedMemorySize, ATTN_SMEM_BYTES);

    // prep
    conv_x_kernel<<<(MROWS * DD / 4 + 255) / 256, 256>>>(x, pxh, MROWS * DD / 4);
    dim3 wgrid(32, 32, 4);
    wt_all_kernel<<<wgrid, 256>>>(Wq, Wk, Wv, Wo, pwqkvt, pwot);

    // fused QKV projection (fp16 out)
    dim3 qkv_grid(3 * DD / 128, MROWS / 128);   // (24, 64)
    gemm_f16_kernel<1><<<qkv_grid, 128, GEMM_SMEM_BYTES>>>(
        pxh, pwqkvt, bq, bk, bv, pQKV, 3 * DD);

    // V transpose per (b,h)
    dim3 vt_grid(SS / 64, HH, BB);
    vt_kernel<<<vt_grid, 256>>>(pQKV, pvt);

    // attention
    dim3 attn_grid(SS / 128, HH, BB);           // (16, 16, 4)
    attn_f16_kernel<<<attn_grid, 256, ATTN_SMEM_BYTES>>>(pQKV, pvt, pctx);

    // output projection (fp32 out)
    dim3 out_grid(DD / 128, MROWS / 128);       // (8, 64)
    gemm_f16_kernel<0><<<out_grid, 128, GEMM_SMEM_BYTES>>>(
        pctx, pwot, bo, bo, bo, out, DD);
}